// round 2
// baseline (speedup 1.0000x reference)
#include <cuda_runtime.h>

// Problem constants (fixed by the dataset)
#define N_NODES 10000
#define N_EDGES 320000
#define D_FEAT  128
#define OUT_DIM 128
#define SCALES  3
#define KDIM    384   // SCALES * OUT_DIM

// Per-node precomputed layer-1 partials:
//   g_NA[n*384 + s*128 + o] = sum_f nf[n][f] * W1[s][f][o]
//   g_NB[n*384 + s*128 + o] = sum_f nf[n][f] * W1[s][128+f][o]
__device__ __align__(16) float g_NA[N_NODES * KDIM];
__device__ __align__(16) float g_NB[N_NODES * KDIM];

// Edge-index dtype flag: 1 if the buffer is int64, 0 if int32.
__device__ int g_idx64;

// ---------------------------------------------------------------------------
// Kernel 0: detect edge_index dtype. JAX with default x64-disabled config
// silently downcasts jnp.int64 -> int32, so the buffer may be either. For
// int64 (little-endian, values in [0,10000)) every odd 32-bit word is zero.
// ---------------------------------------------------------------------------
__global__ void detect_idx_kernel(const int* __restrict__ ei_raw) {
    if (threadIdx.x == 0 && blockIdx.x == 0) {
        int is64 = 1;
        for (int i = 0; i < 128; i++) {
            if (ei_raw[2 * i + 1] != 0) { is64 = 0; break; }
        }
        g_idx64 = is64;
    }
}

// ---------------------------------------------------------------------------
// Kernel 1: node precompute GEMM.
// C[64 nodes x 128 cols] = nf_tile[64x128] @ W1_slice[128x128]
// grid = (ceil(10000/64)=157, 6); blockIdx.y: c%3 = scale, c/3 = part (NA/NB)
// ---------------------------------------------------------------------------
__global__ __launch_bounds__(256, 1)
void node_pre_kernel(const float* __restrict__ nf,
                     const float* __restrict__ W1) {
    extern __shared__ float sm1[];
    float* As = sm1;              // [128][68]
    float* Bs = sm1 + 128 * 68;   // [128][128]

    const int tid  = threadIdx.x;
    const int c    = blockIdx.y;
    const int s    = c % 3;
    const int part = c / 3;
    const int n0   = blockIdx.x * 64;

    const float* Wbase = W1 + s * (257 * 128) + part * (128 * 128);

    {
        const float4* w4 = (const float4*)Wbase;
        float4* b4 = (float4*)Bs;
        #pragma unroll
        for (int i = 0; i < 16; i++) b4[tid + i * 256] = w4[tid + i * 256];
    }
    {
        #pragma unroll
        for (int i = 0; i < 8; i++) {
            int idx = tid + i * 256;        // 0..2047
            int m   = idx >> 5;
            int k4  = idx & 31;
            float4 v = make_float4(0.f, 0.f, 0.f, 0.f);
            if (n0 + m < N_NODES) v = ((const float4*)nf)[(n0 + m) * 32 + k4];
            As[(k4 * 4 + 0) * 68 + m] = v.x;
            As[(k4 * 4 + 1) * 68 + m] = v.y;
            As[(k4 * 4 + 2) * 68 + m] = v.z;
            As[(k4 * 4 + 3) * 68 + m] = v.w;
        }
    }
    __syncthreads();

    const int tm = tid >> 4;
    const int tn = tid & 15;

    float acc[4][8];
    #pragma unroll
    for (int i = 0; i < 4; i++)
        #pragma unroll
        for (int j = 0; j < 8; j++) acc[i][j] = 0.f;

    #pragma unroll 8
    for (int k = 0; k < 128; k++) {
        float4 a4  = *(const float4*)&As[k * 68 + tm * 4];
        float4 bb0 = *(const float4*)&Bs[k * 128 + tn * 8];
        float4 bb1 = *(const float4*)&Bs[k * 128 + tn * 8 + 4];
        float a[4] = {a4.x, a4.y, a4.z, a4.w};
        float b[8] = {bb0.x, bb0.y, bb0.z, bb0.w, bb1.x, bb1.y, bb1.z, bb1.w};
        #pragma unroll
        for (int i = 0; i < 4; i++)
            #pragma unroll
            for (int j = 0; j < 8; j++) acc[i][j] += a[i] * b[j];
    }

    float* outg = part ? g_NB : g_NA;
    #pragma unroll
    for (int i = 0; i < 4; i++) {
        int n_node = n0 + tm * 4 + i;
        if (n_node < N_NODES) {
            float* dst = outg + n_node * KDIM + s * 128 + tn * 8;
            *(float4*)dst       = make_float4(acc[i][0], acc[i][1], acc[i][2], acc[i][3]);
            *(float4*)(dst + 4) = make_float4(acc[i][4], acc[i][5], acc[i][6], acc[i][7]);
        }
    }
}

// ---------------------------------------------------------------------------
// Kernel 2: fused edge kernel.
// Per 128-edge tile, per scale s: build h_s = relu(NA[src]+NB[dest]+gap*G+b1)
// in smem (k-major), accumulate acc += h_s @ W2[s]; epilogue out=acc/3+mean(b2).
// ---------------------------------------------------------------------------
__global__ __launch_bounds__(256, 1)
void edge_kernel(const float* __restrict__ temporal,
                 const float* __restrict__ W1,
                 const float* __restrict__ b1,
                 const float* __restrict__ W2,
                 const float* __restrict__ b2,
                 const void* __restrict__ ei,
                 float* __restrict__ out) {
    extern __shared__ float sm2[];
    float* Hs    = sm2;                    // [128][136]
    float* W2s   = sm2 + 128 * 136;        // [128][128]
    float* s_gap = W2s + 128 * 128;        // [128]
    int*   s_src = (int*)(s_gap + 128);    // [128]
    int*   s_dst = s_src + 128;            // [128]

    const int tid = threadIdx.x;
    const int e0  = blockIdx.x * 128;

    if (tid < 128) {
        int sidx, didx;
        if (g_idx64) {
            sidx = (int)((const long long*)ei)[e0 + tid];
            didx = (int)((const long long*)ei)[N_EDGES + e0 + tid];
        } else {
            sidx = ((const int*)ei)[e0 + tid];
            didx = ((const int*)ei)[N_EDGES + e0 + tid];
        }
        s_src[tid] = sidx;
        s_dst[tid] = didx;
        s_gap[tid] = temporal[sidx] - temporal[didx];
    }
    __syncthreads();

    const int tm = tid >> 4;   // edge-row base tm*8
    const int tn = tid & 15;   // out-col base tn*8

    const int hm   = tid >> 1;
    const int half = tid & 1;
    const int src_n = s_src[hm];
    const int dst_n = s_dst[hm];
    const float gap = s_gap[hm];

    float acc[8][8];
    #pragma unroll
    for (int i = 0; i < 8; i++)
        #pragma unroll
        for (int j = 0; j < 8; j++) acc[i][j] = 0.f;

    for (int sc = 0; sc < SCALES; sc++) {
        {
            const float4* w4 = (const float4*)(W2 + sc * (128 * 128));
            float4* d4 = (float4*)W2s;
            #pragma unroll
            for (int i = 0; i < 16; i++) d4[tid + i * 256] = w4[tid + i * 256];
        }
        {
            const float4* na4 = (const float4*)g_NA + src_n * 96 + sc * 32 + half * 16;
            const float4* nb4 = (const float4*)g_NB + dst_n * 96 + sc * 32 + half * 16;
            const float4* g4  = (const float4*)(W1 + sc * (257 * 128) + 256 * 128) + half * 16;
            const float4* bb4 = (const float4*)(b1 + sc * 128) + half * 16;
            #pragma unroll
            for (int i = 0; i < 16; i++) {
                float4 na = na4[i];
                float4 nb = nb4[i];
                float4 gg = g4[i];
                float4 bb = bb4[i];
                int o = half * 64 + i * 4;
                Hs[(o + 0) * 136 + hm] = fmaxf(na.x + nb.x + gap * gg.x + bb.x, 0.f);
                Hs[(o + 1) * 136 + hm] = fmaxf(na.y + nb.y + gap * gg.y + bb.y, 0.f);
                Hs[(o + 2) * 136 + hm] = fmaxf(na.z + nb.z + gap * gg.z + bb.z, 0.f);
                Hs[(o + 3) * 136 + hm] = fmaxf(na.w + nb.w + gap * gg.w + bb.w, 0.f);
            }
        }
        __syncthreads();

        #pragma unroll 4
        for (int k = 0; k < 128; k++) {
            float4 a0  = *(const float4*)&Hs[k * 136 + tm * 8];
            float4 a1  = *(const float4*)&Hs[k * 136 + tm * 8 + 4];
            float4 bb0 = *(const float4*)&W2s[k * 128 + tn * 8];
            float4 bb1 = *(const float4*)&W2s[k * 128 + tn * 8 + 4];
            float a[8] = {a0.x, a0.y, a0.z, a0.w, a1.x, a1.y, a1.z, a1.w};
            float b[8] = {bb0.x, bb0.y, bb0.z, bb0.w, bb1.x, bb1.y, bb1.z, bb1.w};
            #pragma unroll
            for (int i = 0; i < 8; i++)
                #pragma unroll
                for (int j = 0; j < 8; j++) acc[i][j] += a[i] * b[j];
        }
        __syncthreads();
    }

    const float inv3 = 1.0f / 3.0f;
    float b2m[8];
    #pragma unroll
    for (int j = 0; j < 8; j++) {
        int n = tn * 8 + j;
        b2m[j] = (b2[n] + b2[128 + n] + b2[256 + n]) * inv3;
    }
    #pragma unroll
    for (int i = 0; i < 8; i++) {
        int e = e0 + tm * 8 + i;
        float* dst = out + (size_t)e * 128 + tn * 8;
        *(float4*)dst = make_float4(acc[i][0] * inv3 + b2m[0],
                                    acc[i][1] * inv3 + b2m[1],
                                    acc[i][2] * inv3 + b2m[2],
                                    acc[i][3] * inv3 + b2m[3]);
        *(float4*)(dst + 4) = make_float4(acc[i][4] * inv3 + b2m[4],
                                          acc[i][5] * inv3 + b2m[5],
                                          acc[i][6] * inv3 + b2m[6],
                                          acc[i][7] * inv3 + b2m[7]);
    }
}

// ---------------------------------------------------------------------------
// Launch: map inputs by element count (robust to metadata ordering).
// ---------------------------------------------------------------------------
extern "C" void kernel_launch(void* const* d_in, const int* in_sizes, int n_in,
                              void* d_out, int out_size) {
    const float* nf = 0;
    const float* temporal = 0;
    const float* W1 = 0;
    const float* b1 = 0;
    const float* W2 = 0;
    const float* b2 = 0;
    const void*  ei = 0;

    for (int i = 0; i < n_in; i++) {
        switch (in_sizes[i]) {
            case N_NODES * D_FEAT:      nf = (const float*)d_in[i]; break;       // 1,280,000
            case N_NODES:               temporal = (const float*)d_in[i]; break; // 10,000
            case SCALES * 257 * 128:    W1 = (const float*)d_in[i]; break;       // 98,688
            case SCALES * 128 * 128:    W2 = (const float*)d_in[i]; break;       // 49,152
            case 2 * N_EDGES:           ei = d_in[i]; break;                     // 640,000
            case SCALES * 128:                                                   // 384 (b1 then b2)
                if (!b1) b1 = (const float*)d_in[i];
                else     b2 = (const float*)d_in[i];
                break;
            default: break;
        }
    }
    float* out = (float*)d_out;

    const int smem1 = (128 * 68 + 128 * 128) * sizeof(float);
    const int smem2 = (128 * 136 + 128 * 128 + 128) * sizeof(float) + 128 * 2 * sizeof(int);

    cudaFuncSetAttribute(node_pre_kernel, cudaFuncAttributeMaxDynamicSharedMemorySize, smem1);
    cudaFuncSetAttribute(edge_kernel,     cudaFuncAttributeMaxDynamicSharedMemorySize, smem2);

    detect_idx_kernel<<<1, 32>>>((const int*)ei);

    dim3 g1((N_NODES + 63) / 64, 6);
    node_pre_kernel<<<g1, 256, smem1>>>(nf, W1);

    edge_kernel<<<N_EDGES / 128, 256, smem2>>>(temporal, W1, b1, W2, b2, ei, out);
}

// round 5
// speedup vs baseline: 1.7642x; 1.7642x over previous
#include <cuda_runtime.h>
#include <cstdint>

// Problem constants (fixed by the dataset)
#define N_NODES 10000
#define N_EDGES 320000
#define D_FEAT  128
#define OUT_DIM 128
#define SCALES  3
#define KDIM    384
#define NTILES  (N_EDGES / 128)   // 2500

// ---------------------------------------------------------------------------
// Device globals
// ---------------------------------------------------------------------------
__device__ __align__(16) float g_NA[N_NODES * KDIM];
__device__ __align__(16) float g_NB[N_NODES * KDIM];
__device__ __align__(16) float g_b2m[128];
__device__ __align__(16) float c_W1g[SCALES * 128];
__device__ __align__(16) float c_b1g[SCALES * 128];
__device__ int g_idx64;

// ---------------------------------------------------------------------------
// Helpers (baseline PTX only — no sm_103a-suffixed features)
// ---------------------------------------------------------------------------
__device__ __forceinline__ uint32_t f2tf32(float x) {
    uint32_t u; asm("cvt.rna.tf32.f32 %0, %1;" : "=r"(u) : "f"(x)); return u;
}

// m16n8k8 tf32 mma (sm_80+ baseline PTX -> legacy HMMA on Blackwell)
__device__ __forceinline__ void mma_tf32(float c[4],
                                         uint32_t a0, uint32_t a1, uint32_t a2, uint32_t a3,
                                         uint32_t b0, uint32_t b1) {
    asm volatile(
        "mma.sync.aligned.m16n8k8.row.col.f32.tf32.tf32.f32 "
        "{%0,%1,%2,%3}, {%4,%5,%6,%7}, {%8,%9}, {%0,%1,%2,%3};"
        : "+f"(c[0]), "+f"(c[1]), "+f"(c[2]), "+f"(c[3])
        : "r"(a0), "r"(a1), "r"(a2), "r"(a3), "r"(b0), "r"(b1));
}

// ---------------------------------------------------------------------------
// Kernel 0: edge_index dtype detection (JAX x64-off silently gives int32).
// ---------------------------------------------------------------------------
__global__ void detect_idx_kernel(const int* __restrict__ ei_raw) {
    int t = threadIdx.x;  // 128 threads
    int nz = (ei_raw[2 * t + 1] != 0) ? 1 : 0;
    int tot = __syncthreads_count(nz);
    if (t == 0) g_idx64 = (tot == 0) ? 1 : 0;
}

// ---------------------------------------------------------------------------
// Kernel 0b: stage tile-invariant layer-1 rows (gap weight G, b1) + mean b2.
// ---------------------------------------------------------------------------
__global__ void stage_small_kernel(const float* __restrict__ W1,
                                   const float* __restrict__ b1,
                                   const float* __restrict__ b2) {
    int t = blockIdx.x * 128 + threadIdx.x;   // 0..383
    if (t < SCALES * 128) {
        int s = t >> 7, n = t & 127;
        c_W1g[t] = W1[s * (257 * 128) + 256 * 128 + n];
        c_b1g[t] = b1[t];
    }
    if (t < 128) {
        g_b2m[t] = (b2[t] + b2[128 + t] + b2[256 + t]) * (1.0f / 3.0f);
    }
}

// ---------------------------------------------------------------------------
// Kernel 1: node precompute GEMM (exact fp32).
//   g_NA[n][s*128+o] = nf[n] . W1[s][0:128][o]
//   g_NB[n][s*128+o] = nf[n] . W1[s][128:256][o]
// ---------------------------------------------------------------------------
__global__ __launch_bounds__(256, 1)
void node_pre_kernel(const float* __restrict__ nf,
                     const float* __restrict__ W1) {
    extern __shared__ float sm1[];
    float* As = sm1;              // [128][68]
    float* Bs = sm1 + 128 * 68;   // [128][128]

    const int tid  = threadIdx.x;
    const int c    = blockIdx.y;
    const int s    = c % 3;
    const int part = c / 3;
    const int n0   = blockIdx.x * 64;

    const float* Wbase = W1 + s * (257 * 128) + part * (128 * 128);
    {
        const float4* w4 = (const float4*)Wbase;
        float4* b4 = (float4*)Bs;
        #pragma unroll
        for (int i = 0; i < 16; i++) b4[tid + i * 256] = w4[tid + i * 256];
    }
    {
        #pragma unroll
        for (int i = 0; i < 8; i++) {
            int idx = tid + i * 256;
            int m   = idx >> 5;
            int k4  = idx & 31;
            float4 v = make_float4(0.f, 0.f, 0.f, 0.f);
            if (n0 + m < N_NODES) v = ((const float4*)nf)[(n0 + m) * 32 + k4];
            As[(k4 * 4 + 0) * 68 + m] = v.x;
            As[(k4 * 4 + 1) * 68 + m] = v.y;
            As[(k4 * 4 + 2) * 68 + m] = v.z;
            As[(k4 * 4 + 3) * 68 + m] = v.w;
        }
    }
    __syncthreads();

    const int tm = tid >> 4;
    const int tn = tid & 15;
    float acc[4][8];
    #pragma unroll
    for (int i = 0; i < 4; i++)
        #pragma unroll
        for (int j = 0; j < 8; j++) acc[i][j] = 0.f;

    #pragma unroll 8
    for (int k = 0; k < 128; k++) {
        float4 a4  = *(const float4*)&As[k * 68 + tm * 4];
        float4 bb0 = *(const float4*)&Bs[k * 128 + tn * 8];
        float4 bb1 = *(const float4*)&Bs[k * 128 + tn * 8 + 4];
        float a[4] = {a4.x, a4.y, a4.z, a4.w};
        float b[8] = {bb0.x, bb0.y, bb0.z, bb0.w, bb1.x, bb1.y, bb1.z, bb1.w};
        #pragma unroll
        for (int i = 0; i < 4; i++)
            #pragma unroll
            for (int j = 0; j < 8; j++) acc[i][j] += a[i] * b[j];
    }

    float* outg = part ? g_NB : g_NA;
    #pragma unroll
    for (int i = 0; i < 4; i++) {
        int n_node = n0 + tm * 4 + i;
        if (n_node < N_NODES) {
            float* dst = outg + n_node * KDIM + s * 128 + tn * 8;
            *(float4*)dst       = make_float4(acc[i][0], acc[i][1], acc[i][2], acc[i][3]);
            *(float4*)(dst + 4) = make_float4(acc[i][4], acc[i][5], acc[i][6], acc[i][7]);
        }
    }
}

// ---------------------------------------------------------------------------
// Kernel 2: persistent mma.sync tf32 edge kernel.
// grid=148 x 256 threads. 8 warps: warp (wid>>1) -> 32-row m-group,
// (wid&1) -> 64-col n-half. Per 128-edge tile, per scale, K=128 processed in
// four 32-k chunks: all threads build H-chunk (fp32 gather -> relu -> tf32)
// into smem [128][36] (A loads conflict-free), then each warp runs
// 2m x 8n x 4k = 64 m16n8k8 MMAs per chunk. W2 (tf32, stride 136 ->
// conflict-free B loads) staged to smem ONCE per CTA for all 3 scales.
// Accumulators in registers; epilogue: /3 + mean(b2), float2 stores.
// ---------------------------------------------------------------------------
#define W2_STRIDE 136
#define H_STRIDE  36
#define SMEM_W2   0                               // 3*128*136*4 = 208896 B
#define SMEM_H    208896                          // 128*36*4    = 18432 B
#define SMEM_SRC  227328                          // 512 B
#define SMEM_DST  227840                          // 512 B
#define SMEM_GAP  228352                          // 512 B
#define SMEM_TOT  228864

__global__ __launch_bounds__(256, 1)
void edge_kernel(const float* __restrict__ temporal,
                 const float* __restrict__ W2,
                 const void* __restrict__ ei,
                 float* __restrict__ out) {
    extern __shared__ char smem[];
    uint32_t* W2s  = (uint32_t*)(smem + SMEM_W2);   // [(s*128+k)][136]
    uint32_t* Hc   = (uint32_t*)(smem + SMEM_H);    // [128][36]
    int*      s_src = (int*)(smem + SMEM_SRC);
    int*      s_dst = (int*)(smem + SMEM_DST);
    float*    s_gap = (float*)(smem + SMEM_GAP);

    const int tid  = threadIdx.x;
    const int wid  = tid >> 5;
    const int lane = tid & 31;
    const int gid  = lane >> 2;    // group id 0..7
    const int qid  = lane & 3;     // thread-in-group 0..3
    const int mrow0 = (wid >> 1) * 32;
    const int ncol0 = (wid & 1) * 64;
    const int erow = tid >> 1;     // edge row this thread builds
    const int half = tid & 1;      // which 16-col half

    // Stage W2 -> tf32 smem once (all 3 scales).
    for (int i = tid; i < SCALES * 128 * 128; i += 256) {
        int sk = i >> 7;           // s*128 + k
        int n  = i & 127;
        W2s[sk * W2_STRIDE + n] = f2tf32(W2[i]);
    }

    // Per-thread bias registers.
    float2 b2r[8];
    #pragma unroll
    for (int nf = 0; nf < 8; nf++) {
        int col = ncol0 + nf * 8 + qid * 2;
        b2r[nf] = *(const float2*)(g_b2m + col);
    }

    const int idx64 = g_idx64;
    const float inv3 = 1.0f / 3.0f;

    __syncthreads();

    for (int tt = blockIdx.x; tt < NTILES; tt += gridDim.x) {
        const int e0 = tt * 128;
        if (tid < 128) {
            int si, di;
            if (idx64) {
                si = (int)((const long long*)ei)[e0 + tid];
                di = (int)((const long long*)ei)[N_EDGES + e0 + tid];
            } else {
                si = ((const int*)ei)[e0 + tid];
                di = ((const int*)ei)[N_EDGES + e0 + tid];
            }
            s_src[tid] = si; s_dst[tid] = di;
            s_gap[tid] = temporal[si] - temporal[di];
        }
        __syncthreads();

        const int   src_n = s_src[erow];
        const int   dst_n = s_dst[erow];
        const float gap   = s_gap[erow];

        float c[2][8][4];
        #pragma unroll
        for (int mf = 0; mf < 2; mf++)
            #pragma unroll
            for (int nf = 0; nf < 8; nf++)
                #pragma unroll
                for (int q = 0; q < 4; q++) c[mf][nf][q] = 0.f;

        for (int s = 0; s < SCALES; s++) {
            const float4* naP = (const float4*)(g_NA + (size_t)src_n * KDIM + s * 128);
            const float4* nbP = (const float4*)(g_NB + (size_t)dst_n * KDIM + s * 128);
            const float4* gP  = (const float4*)(c_W1g + s * 128);
            const float4* bP  = (const float4*)(c_b1g + s * 128);

            for (int ch = 0; ch < 4; ch++) {
                // Build H chunk: cols [ch*32, ch*32+32) of h_s, all 128 rows.
                {
                    const int fbase = ch * 8 + half * 4;
                    uint32_t* hdst = Hc + erow * H_STRIDE + half * 16;
                    #pragma unroll
                    for (int i = 0; i < 4; i++) {
                        float4 na = naP[fbase + i];
                        float4 nb = nbP[fbase + i];
                        float4 gg = gP[fbase + i];
                        float4 bb = bP[fbase + i];
                        uint4 hv;
                        hv.x = f2tf32(fmaxf(na.x + nb.x + gap * gg.x + bb.x, 0.f));
                        hv.y = f2tf32(fmaxf(na.y + nb.y + gap * gg.y + bb.y, 0.f));
                        hv.z = f2tf32(fmaxf(na.z + nb.z + gap * gg.z + bb.z, 0.f));
                        hv.w = f2tf32(fmaxf(na.w + nb.w + gap * gg.w + bb.w, 0.f));
                        ((uint4*)hdst)[i] = hv;
                    }
                }
                __syncthreads();

                const uint32_t* wbase = W2s + (s * 128 + ch * 32) * W2_STRIDE + ncol0;
                #pragma unroll
                for (int kf = 0; kf < 4; kf++) {
                    // B fragments (k = ch*32 + kf*8 + {qid, qid+4}, n = ncol0 + nf*8 + gid)
                    uint32_t bfr[8][2];
                    const uint32_t* wb = wbase + kf * 8 * W2_STRIDE;
                    #pragma unroll
                    for (int nf = 0; nf < 8; nf++) {
                        bfr[nf][0] = wb[qid * W2_STRIDE + nf * 8 + gid];
                        bfr[nf][1] = wb[(qid + 4) * W2_STRIDE + nf * 8 + gid];
                    }
                    #pragma unroll
                    for (int mf = 0; mf < 2; mf++) {
                        const uint32_t* ha = Hc + (mrow0 + mf * 16 + gid) * H_STRIDE + kf * 8;
                        uint32_t a0 = ha[qid];
                        uint32_t a1 = ha[8 * H_STRIDE + qid];
                        uint32_t a2 = ha[qid + 4];
                        uint32_t a3 = ha[8 * H_STRIDE + qid + 4];
                        #pragma unroll
                        for (int nf = 0; nf < 8; nf++)
                            mma_tf32(c[mf][nf], a0, a1, a2, a3, bfr[nf][0], bfr[nf][1]);
                    }
                }
                __syncthreads();
            }
        }

        // Epilogue: out = acc/3 + mean(b2)
        #pragma unroll
        for (int mf = 0; mf < 2; mf++) {
            const size_t r0 = (size_t)(e0 + mrow0 + mf * 16 + gid);
            #pragma unroll
            for (int nf = 0; nf < 8; nf++) {
                int col = ncol0 + nf * 8 + qid * 2;
                float2 lo = make_float2(c[mf][nf][0] * inv3 + b2r[nf].x,
                                        c[mf][nf][1] * inv3 + b2r[nf].y);
                float2 hi = make_float2(c[mf][nf][2] * inv3 + b2r[nf].x,
                                        c[mf][nf][3] * inv3 + b2r[nf].y);
                *(float2*)(out + r0 * 128 + col)       = lo;
                *(float2*)(out + (r0 + 8) * 128 + col) = hi;
            }
        }
    }
}

// ---------------------------------------------------------------------------
// Launch
// ---------------------------------------------------------------------------
extern "C" void kernel_launch(void* const* d_in, const int* in_sizes, int n_in,
                              void* d_out, int out_size) {
    const float* nf = 0;
    const float* temporal = 0;
    const float* W1 = 0;
    const float* b1 = 0;
    const float* W2 = 0;
    const float* b2 = 0;
    const void*  ei = 0;

    for (int i = 0; i < n_in; i++) {
        switch (in_sizes[i]) {
            case N_NODES * D_FEAT:   nf = (const float*)d_in[i]; break;
            case N_NODES:            temporal = (const float*)d_in[i]; break;
            case SCALES * 257 * 128: W1 = (const float*)d_in[i]; break;
            case SCALES * 128 * 128: W2 = (const float*)d_in[i]; break;
            case 2 * N_EDGES:        ei = d_in[i]; break;
            case SCALES * 128:
                if (!b1) b1 = (const float*)d_in[i];
                else     b2 = (const float*)d_in[i];
                break;
            default: break;
        }
    }
    float* out = (float*)d_out;

    const int smem1 = (128 * 68 + 128 * 128) * sizeof(float);
    cudaFuncSetAttribute(node_pre_kernel, cudaFuncAttributeMaxDynamicSharedMemorySize, smem1);
    cudaFuncSetAttribute(edge_kernel,     cudaFuncAttributeMaxDynamicSharedMemorySize, SMEM_TOT);

    detect_idx_kernel<<<1, 128>>>((const int*)ei);
    stage_small_kernel<<<3, 128>>>(W1, b1, b2);

    dim3 g1((N_NODES + 63) / 64, 6);
    node_pre_kernel<<<g1, 256, smem1>>>(nf, W1);

    edge_kernel<<<148, 256, SMEM_TOT>>>(temporal, W2, ei, out);
}